// round 8
// baseline (speedup 1.0000x reference)
#include <cuda_runtime.h>
#include <math.h>

// MinDistLoss: out = min_{b,n,m} sqrt(max( xx[b,n] + yy[b,m] - 2*dot(v1[b,n],v2[b,m]), 0 ))
//
// FROZEN numeric scheme (bit-exact vs reference, rel_err = 0.0 since round 1):
//   xx = (x0*x0 + x1*x1) + x2*x2         (separate mul/add)
//   dot = fma(z,z', fma(y,y', x*x'))     (ascending fma chain)
//   sq = fma(-2, dot, xx+yy)
// R7 equivalence: b-side pre-scaled by exact -2 =>
//   e = fma(az,-2bz, fma(ay,-2by, ax*(-2bx))) == -2*dot  EXACTLY,
//   sq = (xx+yy) + e  == fma(-2,dot,xx+yy)  bit-for-bit.
//
// R8: the entire per-group computation (5 f32x2 ops + unpack + 2 mins) is ONE
// asm block with internal .b64 temps, so no register-pair MOVs are forced at
// asm boundaries. Counters showed fma ops were only ~52% of the issued stream
// vs ~71% expected -> hidden MOV tax between the separate asm statements.

#define TN 256
#define TM 128
#define THREADS 256
#define MCHUNKS 4
#define FLT_MAX_BITS 0x7f7fffffu

__device__ unsigned g_minbits = FLT_MAX_BITS;
__device__ unsigned g_count   = 0;

typedef unsigned long long u64;

__device__ __forceinline__ u64 pack2(float lo, float hi) {
    u64 r; asm("mov.b64 %0, {%1, %2};" : "=l"(r) : "f"(lo), "f"(hi)); return r;
}

// One group: 2 pairs. e = ax*bx' + ay*by' + az*bz'  (b' pre-scaled by -2),
// sq = (aw + bw) + e ; running mins updated in-place.
__device__ __forceinline__ void group_min(float& b0, float& b1,
                                          u64 ax, u64 ay, u64 az, u64 aw,
                                          u64 bx, u64 by, u64 bz, u64 bw) {
    asm("{\n\t"
        ".reg .b64 e, t;\n\t"
        ".reg .f32 lo, hi;\n\t"
        "mul.rn.f32x2 e, %2, %3;\n\t"
        "fma.rn.f32x2 e, %4, %5, e;\n\t"
        "fma.rn.f32x2 e, %6, %7, e;\n\t"
        "add.rn.f32x2 t, %8, %9;\n\t"
        "add.rn.f32x2 t, t, e;\n\t"
        "mov.b64 {lo, hi}, t;\n\t"
        "min.f32 %0, %0, lo;\n\t"
        "min.f32 %1, %1, hi;\n\t"
        "}"
        : "+f"(b0), "+f"(b1)
        : "l"(ax), "l"(bx), "l"(ay), "l"(by),
          "l"(az), "l"(bz), "l"(aw), "l"(bw));
}

__global__ __launch_bounds__(THREADS, 4)
void pairmin_kernel(const float* __restrict__ v1, const float* __restrict__ v2,
                    int B, int N, int M, int nblocks, float* __restrict__ out) {
    // a-strip: sa0[n] = {ax2, ay2}, sa1[n] = {az2, aw2}  (duplicated {v,v} pairs)
    // b-tile : sb0[p] = {-2bx2, -2by2}, sb1[p] = {-2bz2, bw2}  (natural {m,m+1})
    __shared__ ulonglong2 sa0[TN], sa1[TN];
    __shared__ ulonglong2 sb0[TM / 2], sb1[TM / 2];

    const int b     = blockIdx.z;
    const int n0    = blockIdx.y * TN;
    const int chunk = blockIdx.x;
    const float* p1 = v1 + (size_t)b * N * 3;
    const float* p2 = v2 + (size_t)b * M * 3;
    const int tid = threadIdx.x;
    const int MT  = (M + TM - 1) / TM;   // m-tiles total

    // ---- Stage a-strip once ----
    {
        int n = n0 + tid; if (n > N - 1) n = N - 1;
        float x0 = p1[n * 3 + 0], x1 = p1[n * 3 + 1], x2 = p1[n * 3 + 2];
        float w = __fadd_rn(__fadd_rn(__fmul_rn(x0, x0), __fmul_rn(x1, x1)),
                            __fmul_rn(x2, x2));
        sa0[tid] = make_ulonglong2(pack2(x0, x0), pack2(x1, x1));
        sa1[tid] = make_ulonglong2(pack2(x2, x2), pack2(w, w));
    }

    const int tx = tid & 15;   // b-group: 4 pairs at slots jp*16 + tx (conflict-free)
    const int ty = tid >> 4;   // a-group: 16 n rows ty*16 + i

    float bst[8];
#pragma unroll
    for (int k = 0; k < 8; k++) bst[k] = 3.4028235e38f;

    // ---- Prologue: stage first b-tile ----
    float gy0 = 0.f, gy1 = 0.f, gy2 = 0.f;
    int t0 = chunk;  // tiles: chunk, chunk+MCHUNKS, ...
    if (tid < TM && t0 < MT) {
        int m = t0 * TM + tid; if (m > M - 1) m = M - 1;
        gy0 = p2[m * 3 + 0]; gy1 = p2[m * 3 + 1]; gy2 = p2[m * 3 + 2];
    }
    if (tid < TM) {
        float w = __fadd_rn(__fadd_rn(__fmul_rn(gy0, gy0), __fmul_rn(gy1, gy1)),
                            __fmul_rn(gy2, gy2));
        float* f0 = (float*)sb0;   // pair p: [-2y0_lo, -2y0_hi, -2y1_lo, -2y1_hi]
        float* f1 = (float*)sb1;   // pair p: [-2y2_lo, -2y2_hi,  w_lo,    w_hi ]
        int p = tid >> 1, h = tid & 1;
        f0[p * 4 + 0 + h] = __fmul_rn(-2.0f, gy0);
        f0[p * 4 + 2 + h] = __fmul_rn(-2.0f, gy1);
        f1[p * 4 + 0 + h] = __fmul_rn(-2.0f, gy2);
        f1[p * 4 + 2 + h] = w;
    }
    __syncthreads();

    for (int t = t0; t < MT; t += MCHUNKS) {
        // Load b-tile into compute registers
        u64 bx2[4], by2[4], bz2[4], bw2[4];
#pragma unroll
        for (int jp = 0; jp < 4; jp++) {
            int s = jp * 16 + tx;
            ulonglong2 B0 = sb0[s], B1 = sb1[s];
            bx2[jp] = B0.x; by2[jp] = B0.y; bz2[jp] = B1.x; bw2[jp] = B1.y;
        }

        // Issue next tile's global loads now (latency hidden under mainloop)
        int tn = t + MCHUNKS;
        if (tid < TM && tn < MT) {
            int m = tn * TM + tid; if (m > M - 1) m = M - 1;
            gy0 = p2[m * 3 + 0]; gy1 = p2[m * 3 + 1]; gy2 = p2[m * 3 + 2];
        }

        // ---- Mainloop over 16 a-rows ----
        const ulonglong2* pa0 = &sa0[ty * 16];
        const ulonglong2* pa1 = &sa1[ty * 16];
#pragma unroll 2
        for (int i = 0; i < 16; i++) {
            ulonglong2 A0 = pa0[i], A1 = pa1[i];
            const u64 ax = A0.x, ay = A0.y, az = A1.x, aw = A1.y;
#pragma unroll
            for (int jp = 0; jp < 4; jp++) {
                group_min(bst[jp * 2 + 0], bst[jp * 2 + 1],
                          ax, ay, az, aw,
                          bx2[jp], by2[jp], bz2[jp], bw2[jp]);
            }
        }

        if (tn < MT) {
            __syncthreads();   // everyone done reading sb for tile t
            if (tid < TM) {
                float w = __fadd_rn(__fadd_rn(__fmul_rn(gy0, gy0), __fmul_rn(gy1, gy1)),
                                    __fmul_rn(gy2, gy2));
                float* f0 = (float*)sb0;
                float* f1 = (float*)sb1;
                int p = tid >> 1, h = tid & 1;
                f0[p * 4 + 0 + h] = __fmul_rn(-2.0f, gy0);
                f0[p * 4 + 2 + h] = __fmul_rn(-2.0f, gy1);
                f1[p * 4 + 0 + h] = __fmul_rn(-2.0f, gy2);
                f1[p * 4 + 2 + h] = w;
            }
            __syncthreads();   // sb ready for tile t+MCHUNKS
        }
    }

    float best = fminf(fminf(fminf(bst[0], bst[1]), fminf(bst[2], bst[3])),
                       fminf(fminf(bst[4], bst[5]), fminf(bst[6], bst[7])));

    // Warp reduce
#pragma unroll
    for (int off = 16; off; off >>= 1)
        best = fminf(best, __shfl_xor_sync(0xffffffffu, best, off));

    __shared__ float wmin[THREADS / 32];
    if ((tid & 31) == 0) wmin[tid >> 5] = best;
    __syncthreads();

    if (tid == 0) {
        float r = wmin[0];
#pragma unroll
        for (int w = 1; w < THREADS / 32; w++) r = fminf(r, wmin[w]);
        atomicMin(&g_minbits, __float_as_uint(fmaxf(r, 0.0f)));
        __threadfence();
        unsigned ticket = atomicAdd(&g_count, 1);
        if (ticket == (unsigned)(nblocks - 1)) {
            // last block: read-and-reset (deterministic across graph replays)
            unsigned bits = atomicExch(&g_minbits, FLT_MAX_BITS);
            atomicExch(&g_count, 0u);
            out[0] = sqrtf(__uint_as_float(bits));
        }
    }
}

extern "C" void kernel_launch(void* const* d_in, const int* in_sizes, int n_in,
                              void* d_out, int out_size) {
    const float* v1 = (const float*)d_in[0];
    const float* v2 = (const float*)d_in[1];
    float* out = (float*)d_out;

    const int B = 16;
    const int N = in_sizes[0] / (B * 3);
    const int M = in_sizes[1] / (B * 3);

    dim3 grid(MCHUNKS, (N + TN - 1) / TN, B);
    int nblocks = (int)(grid.x * grid.y * grid.z);

    pairmin_kernel<<<grid, THREADS>>>(v1, v2, B, N, M, nblocks, out);
}

// round 9
// speedup vs baseline: 1.0437x; 1.0437x over previous
#include <cuda_runtime.h>
#include <math.h>

// MinDistLoss: out = min_{b,n,m} sqrt(max( xx[b,n] + yy[b,m] - 2*dot(v1[b,n],v2[b,m]), 0 ))
//
// FROZEN numeric scheme (bit-exact vs reference, rel_err = 0.0 since round 1):
//   xx = (x0*x0 + x1*x1) + x2*x2         (separate mul/add)
//   dot = fma(z,z', fma(y,y', x*x'))     (ascending fma chain)
//   sq = fma(-2, dot, xx+yy)
// R7 equivalence: b-side pre-scaled by exact -2 =>
//   e = fma(az,-2bz, fma(ay,-2by, ax*(-2bx))) == -2*dot  EXACTLY,
//   sq = (xx+yy) + e  == fma(-2,dot,xx+yy)  bit-for-bit.
//
// R9: kill non-fma instruction overhead. Counters show the issue stream is only
// ~50% fma ops vs ~67% hand-counted -> rolled-loop LDS addressing (IMAD/LEA per
// trip) + loop bookkeeping. Fully unroll the 16-row loop with a precomputed row
// base pointer so LDS gets immediate offsets and branches vanish.

#define TN 256
#define TM 128
#define THREADS 256
#define MCHUNKS 4
#define FLT_MAX_BITS 0x7f7fffffu

__device__ unsigned g_minbits = FLT_MAX_BITS;
__device__ unsigned g_count   = 0;

typedef unsigned long long u64;

__device__ __forceinline__ u64 pack2(float lo, float hi) {
    u64 r; asm("mov.b64 %0, {%1, %2};" : "=l"(r) : "f"(lo), "f"(hi)); return r;
}
__device__ __forceinline__ void unpack2(u64 v, float& lo, float& hi) {
    asm("mov.b64 {%0, %1}, %2;" : "=f"(lo), "=f"(hi) : "l"(v));
}
__device__ __forceinline__ u64 mul2(u64 a, u64 b) {
    u64 r; asm("mul.rn.f32x2 %0, %1, %2;" : "=l"(r) : "l"(a), "l"(b)); return r;
}
__device__ __forceinline__ u64 add2(u64 a, u64 b) {
    u64 r; asm("add.rn.f32x2 %0, %1, %2;" : "=l"(r) : "l"(a), "l"(b)); return r;
}
__device__ __forceinline__ u64 fma2(u64 a, u64 b, u64 c) {
    u64 r; asm("fma.rn.f32x2 %0, %1, %2, %3;" : "=l"(r) : "l"(a), "l"(b), "l"(c)); return r;
}

__global__ __launch_bounds__(THREADS, 4)
void pairmin_kernel(const float* __restrict__ v1, const float* __restrict__ v2,
                    int B, int N, int M, int nblocks, float* __restrict__ out) {
    // a-strip: sa0[n] = {ax2, ay2}, sa1[n] = {az2, aw2}  (duplicated {v,v} pairs)
    // b-tile : sb0[p] = {-2bx2, -2by2}, sb1[p] = {-2bz2, bw2}  (natural {m,m+1})
    __shared__ ulonglong2 sa0[TN], sa1[TN];
    __shared__ ulonglong2 sb0[TM / 2], sb1[TM / 2];

    const int b     = blockIdx.z;
    const int n0    = blockIdx.y * TN;
    const int chunk = blockIdx.x;
    const float* p1 = v1 + (size_t)b * N * 3;
    const float* p2 = v2 + (size_t)b * M * 3;
    const int tid = threadIdx.x;
    const int MT  = (M + TM - 1) / TM;   // m-tiles total

    // ---- Stage a-strip once ----
    {
        int n = n0 + tid; if (n > N - 1) n = N - 1;
        float x0 = p1[n * 3 + 0], x1 = p1[n * 3 + 1], x2 = p1[n * 3 + 2];
        float w = __fadd_rn(__fadd_rn(__fmul_rn(x0, x0), __fmul_rn(x1, x1)),
                            __fmul_rn(x2, x2));
        sa0[tid] = make_ulonglong2(pack2(x0, x0), pack2(x1, x1));
        sa1[tid] = make_ulonglong2(pack2(x2, x2), pack2(w, w));
    }

    const int tx = tid & 15;   // b-group: 4 pairs at slots jp*16 + tx (conflict-free)
    const int ty = tid >> 4;   // a-group: 16 n rows ty*16 + i

    float bst[8];
#pragma unroll
    for (int k = 0; k < 8; k++) bst[k] = 3.4028235e38f;

    // ---- Prologue: stage first b-tile ----
    float gy0 = 0.f, gy1 = 0.f, gy2 = 0.f;
    int t0 = chunk;  // tiles: chunk, chunk+MCHUNKS, ...
    if (tid < TM && t0 < MT) {
        int m = t0 * TM + tid; if (m > M - 1) m = M - 1;
        gy0 = p2[m * 3 + 0]; gy1 = p2[m * 3 + 1]; gy2 = p2[m * 3 + 2];
    }
    if (tid < TM) {
        float w = __fadd_rn(__fadd_rn(__fmul_rn(gy0, gy0), __fmul_rn(gy1, gy1)),
                            __fmul_rn(gy2, gy2));
        float* f0 = (float*)sb0;   // pair p: [-2y0_lo, -2y0_hi, -2y1_lo, -2y1_hi]
        float* f1 = (float*)sb1;   // pair p: [-2y2_lo, -2y2_hi,  w_lo,    w_hi ]
        int p = tid >> 1, h = tid & 1;
        f0[p * 4 + 0 + h] = __fmul_rn(-2.0f, gy0);
        f0[p * 4 + 2 + h] = __fmul_rn(-2.0f, gy1);
        f1[p * 4 + 0 + h] = __fmul_rn(-2.0f, gy2);
        f1[p * 4 + 2 + h] = w;
    }
    __syncthreads();

    // Row base pointers (computed once; full unroll below folds i*16B into
    // the LDS immediate offset — no per-trip address arithmetic).
    const ulonglong2* __restrict__ pa0 = sa0 + ty * 16;
    const ulonglong2* __restrict__ pa1 = sa1 + ty * 16;

    for (int t = t0; t < MT; t += MCHUNKS) {
        // Load b-tile into compute registers
        u64 bx2[4], by2[4], bz2[4], bw2[4];
#pragma unroll
        for (int jp = 0; jp < 4; jp++) {
            int s = jp * 16 + tx;
            ulonglong2 B0 = sb0[s], B1 = sb1[s];
            bx2[jp] = B0.x; by2[jp] = B0.y; bz2[jp] = B1.x; bw2[jp] = B1.y;
        }

        // Issue next tile's global loads now (latency hidden under mainloop)
        int tn = t + MCHUNKS;
        if (tid < TM && tn < MT) {
            int m = tn * TM + tid; if (m > M - 1) m = M - 1;
            gy0 = p2[m * 3 + 0]; gy1 = p2[m * 3 + 1]; gy2 = p2[m * 3 + 2];
        }

        // ---- Mainloop over 16 a-rows, fully unrolled ----
#pragma unroll
        for (int i = 0; i < 16; i++) {
            ulonglong2 A0 = pa0[i], A1 = pa1[i];
            const u64 ax = A0.x, ay = A0.y, az = A1.x, aw = A1.y;
#pragma unroll
            for (int jp = 0; jp < 4; jp++) {
                u64 e = mul2(ax, bx2[jp]);          // -2*x*x' (exact scaled chain)
                e = fma2(ay, by2[jp], e);
                e = fma2(az, bz2[jp], e);           // e == -2*dot_chain exactly
                u64 tt = add2(aw, bw2[jp]);         // xx + yy
                u64 sq = add2(tt, e);               // == fma(-2,dot,xx+yy) bitwise
                float lo, hi;
                unpack2(sq, lo, hi);
                bst[jp * 2 + 0] = fminf(bst[jp * 2 + 0], lo);
                bst[jp * 2 + 1] = fminf(bst[jp * 2 + 1], hi);
            }
        }

        if (tn < MT) {
            __syncthreads();   // everyone done reading sb for tile t
            if (tid < TM) {
                float w = __fadd_rn(__fadd_rn(__fmul_rn(gy0, gy0), __fmul_rn(gy1, gy1)),
                                    __fmul_rn(gy2, gy2));
                float* f0 = (float*)sb0;
                float* f1 = (float*)sb1;
                int p = tid >> 1, h = tid & 1;
                f0[p * 4 + 0 + h] = __fmul_rn(-2.0f, gy0);
                f0[p * 4 + 2 + h] = __fmul_rn(-2.0f, gy1);
                f1[p * 4 + 0 + h] = __fmul_rn(-2.0f, gy2);
                f1[p * 4 + 2 + h] = w;
            }
            __syncthreads();   // sb ready for tile t+MCHUNKS
        }
    }

    float best = fminf(fminf(fminf(bst[0], bst[1]), fminf(bst[2], bst[3])),
                       fminf(fminf(bst[4], bst[5]), fminf(bst[6], bst[7])));

    // Warp reduce
#pragma unroll
    for (int off = 16; off; off >>= 1)
        best = fminf(best, __shfl_xor_sync(0xffffffffu, best, off));

    __shared__ float wmin[THREADS / 32];
    if ((tid & 31) == 0) wmin[tid >> 5] = best;
    __syncthreads();

    if (tid == 0) {
        float r = wmin[0];
#pragma unroll
        for (int w = 1; w < THREADS / 32; w++) r = fminf(r, wmin[w]);
        atomicMin(&g_minbits, __float_as_uint(fmaxf(r, 0.0f)));
        __threadfence();
        unsigned ticket = atomicAdd(&g_count, 1);
        if (ticket == (unsigned)(nblocks - 1)) {
            // last block: read-and-reset (deterministic across graph replays)
            unsigned bits = atomicExch(&g_minbits, FLT_MAX_BITS);
            atomicExch(&g_count, 0u);
            out[0] = sqrtf(__uint_as_float(bits));
        }
    }
}

extern "C" void kernel_launch(void* const* d_in, const int* in_sizes, int n_in,
                              void* d_out, int out_size) {
    const float* v1 = (const float*)d_in[0];
    const float* v2 = (const float*)d_in[1];
    float* out = (float*)d_out;

    const int B = 16;
    const int N = in_sizes[0] / (B * 3);
    const int M = in_sizes[1] / (B * 3);

    dim3 grid(MCHUNKS, (N + TN - 1) / TN, B);
    int nblocks = (int)(grid.x * grid.y * grid.z);

    pairmin_kernel<<<grid, THREADS>>>(v1, v2, B, N, M, nblocks, out);
}